// round 4
// baseline (speedup 1.0000x reference)
#include <cuda_runtime.h>
#include <math.h>

#define B_   16
#define N_   4096
#define C_   1152
#define H_   16
#define HD_  72
#define KV2  144          // 2*HD
#define NCAT 1296         // C_ + KV2
#define MTOT (B_*N_)      // 65536

// ---------------- scratch (static device globals; no runtime alloc) -------
__device__ float g_q[(size_t)MTOT * C_];        // 302 MB  q = x@wq + b
__device__ float g_kvlin[(size_t)MTOT * KV2];   // 37.7 MB [k|v]
__device__ float g_vd[(size_t)MTOT * HD_];      // 18.9 MB depthwise conv out
__device__ float g_kv[B_ * HD_ * HD_];          // kv = k_f^T @ v  (per batch)
__device__ float g_M[(size_t)B_ * C_ * C_];     // 85 MB  blockdiag(kv)@proj
__device__ float g_projsum[HD_ * C_];           // sum_h proj rows
__device__ float g_qsum[B_ * H_ * 2];           // {sum r^2, sum r^6} per (b,h)
__device__ float g_ksum[B_ * 2];                // per b
__device__ float g_scaleq[B_ * H_];
__device__ float g_scalek[B_];

// ---------------- init: zero accumulators ---------------------------------
__global__ void k_init() {
    int i = blockIdx.x * blockDim.x + threadIdx.x;
    if (i < B_ * HD_ * HD_) g_kv[i] = 0.f;
    if (i < B_ * H_ * 2)    g_qsum[i] = 0.f;
    if (i < B_ * 2)         g_ksum[i] = 0.f;
}

// ---------------- shared GEMM micro-kernel --------------------------------
template <int KK>
__device__ __forceinline__ void mma_tile(const float As[16][132],
                                         const float Bs[16][128],
                                         float (&acc)[8][8], int ty, int tx) {
#pragma unroll
    for (int k = 0; k < KK; k++) {
        float4 a0 = *(const float4*)&As[k][ty * 8];
        float4 a1 = *(const float4*)&As[k][ty * 8 + 4];
        float4 b0 = *(const float4*)&Bs[k][tx * 8];
        float4 b1 = *(const float4*)&Bs[k][tx * 8 + 4];
        float a[8] = {a0.x, a0.y, a0.z, a0.w, a1.x, a1.y, a1.z, a1.w};
        float b[8] = {b0.x, b0.y, b0.z, b0.w, b1.x, b1.y, b1.z, b1.w};
#pragma unroll
        for (int i = 0; i < 8; i++)
#pragma unroll
            for (int j = 0; j < 8; j++) acc[i][j] += a[i] * b[j];
    }
}

// ---------------- GEMM1: Y = x @ [wq | wkv] + bias ------------------------
// grid (11, 512), block 256.  Writes q part -> g_q, kv part -> g_kvlin.
__global__ __launch_bounds__(256) void k_gemm1(
    const float* __restrict__ x,
    const float* __restrict__ wq,  const float* __restrict__ wqb,
    const float* __restrict__ wkv, const float* __restrict__ wkvb) {
    __shared__ float As[16][132];
    __shared__ float Bs[16][128];
    int tid = threadIdx.x;
    int m0 = blockIdx.y * 128;
    int n0 = blockIdx.x * 128;
    int tx = tid & 15, ty = tid >> 4;
    float acc[8][8] = {};

    for (int kt = 0; kt < C_; kt += 16) {
#pragma unroll
        for (int e = tid; e < 2048; e += 256) {
            int r = e >> 4, kk = e & 15;
            As[kk][r] = x[(size_t)(m0 + r) * C_ + kt + kk];
        }
#pragma unroll
        for (int e = tid; e < 2048; e += 256) {
            int kk = e >> 7, cc = e & 127;
            int n = n0 + cc;
            float bv;
            if (n < C_)         bv = wq[(size_t)(kt + kk) * C_ + n];
            else if (n < NCAT)  bv = wkv[(size_t)(kt + kk) * KV2 + (n - C_)];
            else                bv = 0.f;
            Bs[kk][cc] = bv;
        }
        __syncthreads();
        mma_tile<16>(As, Bs, acc, ty, tx);
        __syncthreads();
    }

#pragma unroll
    for (int i = 0; i < 8; i++) {
        int m = m0 + ty * 8 + i;
#pragma unroll
        for (int j = 0; j < 8; j++) {
            int n = n0 + tx * 8 + j;
            float v = acc[i][j];
            if (n < C_)
                g_q[(size_t)m * C_ + n] = v + wqb[n];
            else if (n < NCAT)
                g_kvlin[(size_t)m * KV2 + (n - C_)] = v + wkvb[n - C_];
        }
    }
}

// ---------------- block reduce two floats ----------------------------------
__device__ __forceinline__ void block_reduce2(float& s2, float& s6) {
#pragma unroll
    for (int o = 16; o; o >>= 1) {
        s2 += __shfl_down_sync(0xffffffffu, s2, o);
        s6 += __shfl_down_sync(0xffffffffu, s6, o);
    }
    __shared__ float sh2[8], sh6[8];
    int w = threadIdx.x >> 5, l = threadIdx.x & 31;
    if (l == 0) { sh2[w] = s2; sh6[w] = s6; }
    __syncthreads();
    if (threadIdx.x == 0) {
        float a = 0.f, c = 0.f;
#pragma unroll
        for (int i = 0; i < 8; i++) { a += sh2[i]; c += sh6[i]; }
        s2 = a; s6 = c;
    }
}

// ---------------- focused-norm reductions ----------------------------------
// grid 4096 = (bh 256) x (split 16); block 256
__global__ void k_qnorm() {
    int bh = blockIdx.x >> 4;
    int split = blockIdx.x & 15;
    int b = bh >> 4, h = bh & 15;
    const float* base = g_q + (size_t)(b * N_ + split * 256) * C_ + h * HD_;
    float s2 = 0.f, s6 = 0.f;
    for (int e = threadIdx.x; e < 256 * HD_; e += 256) {
        int r = e / HD_, d = e % HD_;
        float v = base[(size_t)r * C_ + d];
        float rr = fmaxf(v, 0.f);
        float r2 = rr * rr;  s2 += r2;
        float r3 = r2 * rr;  s6 += r3 * r3;
    }
    block_reduce2(s2, s6);
    if (threadIdx.x == 0) {
        atomicAdd(&g_qsum[bh * 2], s2);
        atomicAdd(&g_qsum[bh * 2 + 1], s6);
    }
}

// grid 256 = (b 16) x (split 16); block 256
__global__ void k_knorm() {
    int b = blockIdx.x >> 4;
    int split = blockIdx.x & 15;
    const float* base = g_kvlin + (size_t)(b * N_ + split * 256) * KV2;
    float s2 = 0.f, s6 = 0.f;
    for (int e = threadIdx.x; e < 256 * HD_; e += 256) {
        int r = e / HD_, d = e % HD_;
        float v = base[(size_t)r * KV2 + d];
        float rr = fmaxf(v, 0.f);
        float r2 = rr * rr;  s2 += r2;
        float r3 = r2 * rr;  s6 += r3 * r3;
    }
    block_reduce2(s2, s6);
    if (threadIdx.x == 0) {
        atomicAdd(&g_ksum[b * 2], s2);
        atomicAdd(&g_ksum[b * 2 + 1], s6);
    }
}

__global__ void k_scales() {
    int i = threadIdx.x;
    if (i < B_ * H_) {
        float s2 = g_qsum[i * 2], s6 = g_qsum[i * 2 + 1];
        g_scaleq[i] = (s6 > 0.f) ? sqrtf(s2 / s6) : 0.f;
    } else if (i < B_ * H_ + B_) {
        int b = i - B_ * H_;
        float s2 = g_ksum[b * 2], s6 = g_ksum[b * 2 + 1];
        g_scalek[b] = (s6 > 0.f) ? sqrtf(s2 / s6) : 0.f;
    }
}

// ---------------- kv = k_f^T @ v (per batch) --------------------------------
// grid (8 nsplits, 16 b), block 576; each thread owns 9 of 5184 outputs
__global__ __launch_bounds__(576) void k_kvacc() {
    __shared__ float ks[16][72], vs[16][72];
    int b = blockIdx.y;
    int n0 = blockIdx.x * 512;
    int tid = threadIdx.x;
    float acc[9] = {};
    int od[9], oe[9];
#pragma unroll
    for (int j = 0; j < 9; j++) { int o = tid + j * 576; od[j] = o / 72; oe[j] = o % 72; }

    for (int nt = 0; nt < 512; nt += 16) {
        __syncthreads();
        for (int e = tid; e < 16 * 72; e += 576) {
            int r = e / 72, d = e % 72;
            const float* p = g_kvlin + (size_t)(b * N_ + n0 + nt + r) * KV2;
            float kvv = p[d];
            float rr = fmaxf(kvv, 0.f);
            ks[r][d] = rr * rr * rr;
            vs[r][d] = p[72 + d];
        }
        __syncthreads();
#pragma unroll
        for (int r = 0; r < 16; r++)
#pragma unroll
            for (int j = 0; j < 9; j++) acc[j] += ks[r][od[j]] * vs[r][oe[j]];
    }
    float s = g_scalek[b];
#pragma unroll
    for (int j = 0; j < 9; j++)
        atomicAdd(&g_kv[b * 5184 + tid + j * 576], acc[j] * s);
}

// ---------------- depthwise 3x3 conv on v -----------------------------------
// grid 18432, block 256 (one thread per output element)
__global__ void k_dwc(const float* __restrict__ w, const float* __restrict__ bias) {
    int idx = blockIdx.x * blockDim.x + threadIdx.x;
    int d = idx % HD_;
    int t = idx / HD_;
    int n = t % N_;
    int b = t / N_;
    int y = n >> 6, xx = n & 63;
    float acc = bias[d];
#pragma unroll
    for (int ky = 0; ky < 3; ky++) {
        int yy = y + ky - 1;
        if ((unsigned)yy < 64u) {
#pragma unroll
            for (int kx = 0; kx < 3; kx++) {
                int xc = xx + kx - 1;
                if ((unsigned)xc < 64u)
                    acc += g_kvlin[(size_t)(b * N_ + yy * 64 + xc) * KV2 + 72 + d]
                         * w[d * 9 + ky * 3 + kx];
            }
        }
    }
    g_vd[(size_t)(b * N_ + n) * HD_ + d] = acc;
}

// ---------------- proj_sum[d][c] = sum_h proj[h*72+d][c] --------------------
// grid 324, block 256
__global__ void k_projsum(const float* __restrict__ proj) {
    int idx = blockIdx.x * blockDim.x + threadIdx.x;
    if (idx >= HD_ * C_) return;
    int d = idx / C_, c = idx % C_;
    float s = 0.f;
#pragma unroll
    for (int h = 0; h < H_; h++) s += proj[(size_t)(h * HD_ + d) * C_ + c];
    g_projsum[(size_t)d * C_ + c] = s;
}

// ---------------- M[b][h*72+d][c] = sum_e kv[b][d][e] * proj[h*72+e][c] -----
// grid (9 ctiles, 16 h, 16 b), block 256
__global__ __launch_bounds__(256) void k_mker(const float* __restrict__ proj) {
    __shared__ float kvs[72 * 72];
    int b = blockIdx.z, h = blockIdx.y, ct = blockIdx.x;
    int tid = threadIdx.x;
    for (int e = tid; e < 5184; e += 256) kvs[e] = g_kv[b * 5184 + e];
    __syncthreads();
    int c = ct * 128 + (tid & 127);
    int dbase = (tid >> 7) * 36;
    float acc[36] = {};
#pragma unroll 8
    for (int e2 = 0; e2 < 72; e2++) {
        float p = proj[(size_t)(h * HD_ + e2) * C_ + c];
#pragma unroll
        for (int dd = 0; dd < 36; dd++)
            acc[dd] += kvs[(dbase + dd) * 72 + e2] * p;
    }
#pragma unroll
    for (int dd = 0; dd < 36; dd++)
        g_M[(size_t)b * C_ * C_ + (size_t)(h * HD_ + dbase + dd) * C_ + c] = acc[dd];
}

// ---------------- GEMM2: out[b] = focused(q)[b]@M[b] + vd[b]@proj_sum + bias -
// grid (9, 32, 16), block 256
__global__ __launch_bounds__(256) void k_gemm2(const float* __restrict__ projb,
                                               float* __restrict__ out) {
    __shared__ float As[16][132];
    __shared__ float Bs[16][128];
    __shared__ float sq[16];
    int tid = threadIdx.x;
    int b = blockIdx.z;
    int m0 = blockIdx.y * 128;
    int n0 = blockIdx.x * 128;
    int tx = tid & 15, ty = tid >> 4;
    if (tid < 16) sq[tid] = g_scaleq[b * H_ + tid];
    __syncthreads();

    const float* qb = g_q + (size_t)b * N_ * C_;
    const float* Mb = g_M + (size_t)b * C_ * C_;
    float acc[8][8] = {};

    // phase 1: K = 1152 over focused(q) @ M[b]
    for (int kt = 0; kt < C_; kt += 16) {
#pragma unroll
        for (int e = tid; e < 2048; e += 256) {
            int r = e >> 4, kk = e & 15;
            int gk = kt + kk;
            int h = gk / 72;
            float v = qb[(size_t)(m0 + r) * C_ + gk];
            float rr = fmaxf(v, 0.f);
            As[kk][r] = sq[h] * rr * rr * rr;
        }
#pragma unroll
        for (int e = tid; e < 2048; e += 256) {
            int kk = e >> 7, cc = e & 127;
            Bs[kk][cc] = Mb[(size_t)(kt + kk) * C_ + n0 + cc];
        }
        __syncthreads();
        mma_tile<16>(As, Bs, acc, ty, tx);
        __syncthreads();
    }

    // phase 2: K = 72 over vd @ proj_sum
    const float* vdb = g_vd + (size_t)b * N_ * HD_;
    for (int kt = 0; kt < HD_; kt += 8) {
#pragma unroll
        for (int e = tid; e < 1024; e += 256) {
            int r = e >> 3, kk = e & 7;
            As[kk][r] = vdb[(size_t)(m0 + r) * HD_ + kt + kk];
        }
#pragma unroll
        for (int e = tid; e < 1024; e += 256) {
            int kk = e >> 7, cc = e & 127;
            Bs[kk][cc] = g_projsum[(size_t)(kt + kk) * C_ + n0 + cc];
        }
        __syncthreads();
        mma_tile<8>(As, Bs, acc, ty, tx);
        __syncthreads();
    }

#pragma unroll
    for (int i = 0; i < 8; i++) {
        int m = m0 + ty * 8 + i;
#pragma unroll
        for (int j = 0; j < 8; j++) {
            int n = n0 + tx * 8 + j;
            out[(size_t)(b * N_ + m) * C_ + n] = acc[i][j] + projb[n];
        }
    }
}

// ---------------- launch -----------------------------------------------------
extern "C" void kernel_launch(void* const* d_in, const int* in_sizes, int n_in,
                              void* d_out, int out_size) {
    const float* x      = (const float*)d_in[0];
    const float* wq_w   = (const float*)d_in[1];
    const float* wq_b   = (const float*)d_in[2];
    const float* wkv_w  = (const float*)d_in[3];
    const float* wkv_b  = (const float*)d_in[4];
    const float* dwc_w  = (const float*)d_in[5];
    const float* dwc_b  = (const float*)d_in[6];
    const float* proj_w = (const float*)d_in[7];
    const float* proj_b = (const float*)d_in[8];
    float* out = (float*)d_out;

    k_init<<<324, 256>>>();
    k_gemm1<<<dim3(11, 512), 256>>>(x, wq_w, wq_b, wkv_w, wkv_b);
    k_qnorm<<<4096, 256>>>();
    k_knorm<<<256, 256>>>();
    k_scales<<<1, 288>>>();
    k_kvacc<<<dim3(8, 16), 576>>>();
    k_dwc<<<18432, 256>>>(dwc_w, dwc_b);
    k_projsum<<<324, 256>>>(proj_w);
    k_mker<<<dim3(9, 16, 16), 256>>>(proj_w);
    k_gemm2<<<dim3(9, 32, 16), 256>>>(proj_b, out);
}

// round 5
// speedup vs baseline: 1.0030x; 1.0030x over previous
#include <cuda_runtime.h>
#include <math.h>

#define B_   16
#define N_   4096
#define C_   1152
#define H_   16
#define HD_  72
#define KV2  144          // 2*HD
#define NCAT 1296         // C_ + KV2
#define MTOT (B_*N_)      // 65536

// ---------------- scratch (static device globals; no runtime alloc) -------
__device__ float g_q[(size_t)MTOT * C_];        // 302 MB  q = x@wq + b
__device__ float g_kvlin[(size_t)MTOT * KV2];   // 37.7 MB [k|v]
__device__ float g_vd[(size_t)MTOT * HD_];      // 18.9 MB depthwise conv out
__device__ float g_kv[B_ * HD_ * HD_];          // kv = k_f^T @ v  (per batch)
__device__ float g_M[(size_t)B_ * C_ * C_];     // 85 MB  blockdiag(kv)@proj
__device__ float g_projsum[HD_ * C_];           // sum_h proj rows
__device__ float g_qsum[B_ * H_ * 2];           // {sum r^2, sum r^6} per (b,h)
__device__ float g_ksum[B_ * 2];                // per b
__device__ float g_scaleq[B_ * H_];
__device__ float g_scalek[B_];

// ---------------- init: zero accumulators ---------------------------------
__global__ void k_init() {
    int i = blockIdx.x * blockDim.x + threadIdx.x;
    if (i < B_ * HD_ * HD_) g_kv[i] = 0.f;
    if (i < B_ * H_ * 2)    g_qsum[i] = 0.f;
    if (i < B_ * 2)         g_ksum[i] = 0.f;
}

// ---------------- shared GEMM micro-kernel --------------------------------
template <int KK>
__device__ __forceinline__ void mma_tile(const float As[16][132],
                                         const float Bs[16][128],
                                         float (&acc)[8][8], int ty, int tx) {
#pragma unroll
    for (int k = 0; k < KK; k++) {
        float4 a0 = *(const float4*)&As[k][ty * 8];
        float4 a1 = *(const float4*)&As[k][ty * 8 + 4];
        float4 b0 = *(const float4*)&Bs[k][tx * 8];
        float4 b1 = *(const float4*)&Bs[k][tx * 8 + 4];
        float a[8] = {a0.x, a0.y, a0.z, a0.w, a1.x, a1.y, a1.z, a1.w};
        float b[8] = {b0.x, b0.y, b0.z, b0.w, b1.x, b1.y, b1.z, b1.w};
#pragma unroll
        for (int i = 0; i < 8; i++)
#pragma unroll
            for (int j = 0; j < 8; j++) acc[i][j] += a[i] * b[j];
    }
}

// ---------------- GEMM1: Y = x @ [wq | wkv] + bias ------------------------
// grid (11, 512), block 256.  Writes q part -> g_q, kv part -> g_kvlin.
__global__ __launch_bounds__(256) void k_gemm1(
    const float* __restrict__ x,
    const float* __restrict__ wq,  const float* __restrict__ wqb,
    const float* __restrict__ wkv, const float* __restrict__ wkvb) {
    __shared__ float As[16][132];
    __shared__ float Bs[16][128];
    int tid = threadIdx.x;
    int m0 = blockIdx.y * 128;
    int n0 = blockIdx.x * 128;
    int tx = tid & 15, ty = tid >> 4;
    float acc[8][8] = {};

    for (int kt = 0; kt < C_; kt += 16) {
#pragma unroll
        for (int e = tid; e < 2048; e += 256) {
            int r = e >> 4, kk = e & 15;
            As[kk][r] = x[(size_t)(m0 + r) * C_ + kt + kk];
        }
#pragma unroll
        for (int e = tid; e < 2048; e += 256) {
            int kk = e >> 7, cc = e & 127;
            int n = n0 + cc;
            float bv;
            if (n < C_)         bv = wq[(size_t)(kt + kk) * C_ + n];
            else if (n < NCAT)  bv = wkv[(size_t)(kt + kk) * KV2 + (n - C_)];
            else                bv = 0.f;
            Bs[kk][cc] = bv;
        }
        __syncthreads();
        mma_tile<16>(As, Bs, acc, ty, tx);
        __syncthreads();
    }

#pragma unroll
    for (int i = 0; i < 8; i++) {
        int m = m0 + ty * 8 + i;
#pragma unroll
        for (int j = 0; j < 8; j++) {
            int n = n0 + tx * 8 + j;
            float v = acc[i][j];
            if (n < C_)
                g_q[(size_t)m * C_ + n] = v + wqb[n];
            else if (n < NCAT)
                g_kvlin[(size_t)m * KV2 + (n - C_)] = v + wkvb[n - C_];
        }
    }
}

// ---------------- block reduce two floats ----------------------------------
__device__ __forceinline__ void block_reduce2(float& s2, float& s6) {
#pragma unroll
    for (int o = 16; o; o >>= 1) {
        s2 += __shfl_down_sync(0xffffffffu, s2, o);
        s6 += __shfl_down_sync(0xffffffffu, s6, o);
    }
    __shared__ float sh2[8], sh6[8];
    int w = threadIdx.x >> 5, l = threadIdx.x & 31;
    if (l == 0) { sh2[w] = s2; sh6[w] = s6; }
    __syncthreads();
    if (threadIdx.x == 0) {
        float a = 0.f, c = 0.f;
#pragma unroll
        for (int i = 0; i < 8; i++) { a += sh2[i]; c += sh6[i]; }
        s2 = a; s6 = c;
    }
}

// ---------------- focused-norm reductions ----------------------------------
// grid 4096 = (bh 256) x (split 16); block 256
__global__ void k_qnorm() {
    int bh = blockIdx.x >> 4;
    int split = blockIdx.x & 15;
    int b = bh >> 4, h = bh & 15;
    const float* base = g_q + (size_t)(b * N_ + split * 256) * C_ + h * HD_;
    float s2 = 0.f, s6 = 0.f;
    for (int e = threadIdx.x; e < 256 * HD_; e += 256) {
        int r = e / HD_, d = e % HD_;
        float v = base[(size_t)r * C_ + d];
        float rr = fmaxf(v, 0.f);
        float r2 = rr * rr;  s2 += r2;
        float r3 = r2 * rr;  s6 += r3 * r3;
    }
    block_reduce2(s2, s6);
    if (threadIdx.x == 0) {
        atomicAdd(&g_qsum[bh * 2], s2);
        atomicAdd(&g_qsum[bh * 2 + 1], s6);
    }
}

// grid 256 = (b 16) x (split 16); block 256
__global__ void k_knorm() {
    int b = blockIdx.x >> 4;
    int split = blockIdx.x & 15;
    const float* base = g_kvlin + (size_t)(b * N_ + split * 256) * KV2;
    float s2 = 0.f, s6 = 0.f;
    for (int e = threadIdx.x; e < 256 * HD_; e += 256) {
        int r = e / HD_, d = e % HD_;
        float v = base[(size_t)r * KV2 + d];
        float rr = fmaxf(v, 0.f);
        float r2 = rr * rr;  s2 += r2;
        float r3 = r2 * rr;  s6 += r3 * r3;
    }
    block_reduce2(s2, s6);
    if (threadIdx.x == 0) {
        atomicAdd(&g_ksum[b * 2], s2);
        atomicAdd(&g_ksum[b * 2 + 1], s6);
    }
}

__global__ void k_scales() {
    int i = threadIdx.x;
    if (i < B_ * H_) {
        float s2 = g_qsum[i * 2], s6 = g_qsum[i * 2 + 1];
        g_scaleq[i] = (s6 > 0.f) ? sqrtf(s2 / s6) : 0.f;
    } else if (i < B_ * H_ + B_) {
        int b = i - B_ * H_;
        float s2 = g_ksum[b * 2], s6 = g_ksum[b * 2 + 1];
        g_scalek[b] = (s6 > 0.f) ? sqrtf(s2 / s6) : 0.f;
    }
}

// ---------------- kv = k_f^T @ v (per batch) --------------------------------
// grid (8 nsplits, 16 b), block 576; each thread owns 9 of 5184 outputs
__global__ __launch_bounds__(576) void k_kvacc() {
    __shared__ float ks[16][72], vs[16][72];
    int b = blockIdx.y;
    int n0 = blockIdx.x * 512;
    int tid = threadIdx.x;
    float acc[9] = {};
    int od[9], oe[9];
#pragma unroll
    for (int j = 0; j < 9; j++) { int o = tid + j * 576; od[j] = o / 72; oe[j] = o % 72; }

    for (int nt = 0; nt < 512; nt += 16) {
        __syncthreads();
        for (int e = tid; e < 16 * 72; e += 576) {
            int r = e / 72, d = e % 72;
            const float* p = g_kvlin + (size_t)(b * N_ + n0 + nt + r) * KV2;
            float kvv = p[d];
            float rr = fmaxf(kvv, 0.f);
            ks[r][d] = rr * rr * rr;
            vs[r][d] = p[72 + d];
        }
        __syncthreads();
#pragma unroll
        for (int r = 0; r < 16; r++)
#pragma unroll
            for (int j = 0; j < 9; j++) acc[j] += ks[r][od[j]] * vs[r][oe[j]];
    }
    float s = g_scalek[b];
#pragma unroll
    for (int j = 0; j < 9; j++)
        atomicAdd(&g_kv[b * 5184 + tid + j * 576], acc[j] * s);
}

// ---------------- depthwise 3x3 conv on v -----------------------------------
// grid 18432, block 256 (one thread per output element)
__global__ void k_dwc(const float* __restrict__ w, const float* __restrict__ bias) {
    int idx = blockIdx.x * blockDim.x + threadIdx.x;
    int d = idx % HD_;
    int t = idx / HD_;
    int n = t % N_;
    int b = t / N_;
    int y = n >> 6, xx = n & 63;
    float acc = bias[d];
#pragma unroll
    for (int ky = 0; ky < 3; ky++) {
        int yy = y + ky - 1;
        if ((unsigned)yy < 64u) {
#pragma unroll
            for (int kx = 0; kx < 3; kx++) {
                int xc = xx + kx - 1;
                if ((unsigned)xc < 64u)
                    acc += g_kvlin[(size_t)(b * N_ + yy * 64 + xc) * KV2 + 72 + d]
                         * w[d * 9 + ky * 3 + kx];
            }
        }
    }
    g_vd[(size_t)(b * N_ + n) * HD_ + d] = acc;
}

// ---------------- proj_sum[d][c] = sum_h proj[h*72+d][c] --------------------
// grid 324, block 256
__global__ void k_projsum(const float* __restrict__ proj) {
    int idx = blockIdx.x * blockDim.x + threadIdx.x;
    if (idx >= HD_ * C_) return;
    int d = idx / C_, c = idx % C_;
    float s = 0.f;
#pragma unroll
    for (int h = 0; h < H_; h++) s += proj[(size_t)(h * HD_ + d) * C_ + c];
    g_projsum[(size_t)d * C_ + c] = s;
}

// ---------------- M[b][h*72+d][c] = sum_e kv[b][d][e] * proj[h*72+e][c] -----
// grid (9 ctiles, 16 h, 16 b), block 256
__global__ __launch_bounds__(256) void k_mker(const float* __restrict__ proj) {
    __shared__ float kvs[72 * 72];
    int b = blockIdx.z, h = blockIdx.y, ct = blockIdx.x;
    int tid = threadIdx.x;
    for (int e = tid; e < 5184; e += 256) kvs[e] = g_kv[b * 5184 + e];
    __syncthreads();
    int c = ct * 128 + (tid & 127);
    int dbase = (tid >> 7) * 36;
    float acc[36] = {};
#pragma unroll 8
    for (int e2 = 0; e2 < 72; e2++) {
        float p = proj[(size_t)(h * HD_ + e2) * C_ + c];
#pragma unroll
        for (int dd = 0; dd < 36; dd++)
            acc[dd] += kvs[(dbase + dd) * 72 + e2] * p;
    }
#pragma unroll
    for (int dd = 0; dd < 36; dd++)
        g_M[(size_t)b * C_ * C_ + (size_t)(h * HD_ + dbase + dd) * C_ + c] = acc[dd];
}

// ---------------- GEMM2: out[b] = focused(q)[b]@M[b] + vd[b]@proj_sum + bias -
// grid (9, 32, 16), block 256
__global__ __launch_bounds__(256) void k_gemm2(const float* __restrict__ projb,
                                               float* __restrict__ out) {
    __shared__ float As[16][132];
    __shared__ float Bs[16][128];
    __shared__ float sq[16];
    int tid = threadIdx.x;
    int b = blockIdx.z;
    int m0 = blockIdx.y * 128;
    int n0 = blockIdx.x * 128;
    int tx = tid & 15, ty = tid >> 4;
    if (tid < 16) sq[tid] = g_scaleq[b * H_ + tid];
    __syncthreads();

    const float* qb = g_q + (size_t)b * N_ * C_;
    const float* Mb = g_M + (size_t)b * C_ * C_;
    float acc[8][8] = {};

    // phase 1: K = 1152 over focused(q) @ M[b]
    for (int kt = 0; kt < C_; kt += 16) {
#pragma unroll
        for (int e = tid; e < 2048; e += 256) {
            int r = e >> 4, kk = e & 15;
            int gk = kt + kk;
            int h = gk / 72;
            float v = qb[(size_t)(m0 + r) * C_ + gk];
            float rr = fmaxf(v, 0.f);
            As[kk][r] = sq[h] * rr * rr * rr;
        }
#pragma unroll
        for (int e = tid; e < 2048; e += 256) {
            int kk = e >> 7, cc = e & 127;
            Bs[kk][cc] = Mb[(size_t)(kt + kk) * C_ + n0 + cc];
        }
        __syncthreads();
        mma_tile<16>(As, Bs, acc, ty, tx);
        __syncthreads();
    }

    // phase 2: K = 72 over vd @ proj_sum
    const float* vdb = g_vd + (size_t)b * N_ * HD_;
    for (int kt = 0; kt < HD_; kt += 8) {
#pragma unroll
        for (int e = tid; e < 1024; e += 256) {
            int r = e >> 3, kk = e & 7;
            As[kk][r] = vdb[(size_t)(m0 + r) * HD_ + kt + kk];
        }
#pragma unroll
        for (int e = tid; e < 1024; e += 256) {
            int kk = e >> 7, cc = e & 127;
            Bs[kk][cc] = g_projsum[(size_t)(kt + kk) * C_ + n0 + cc];
        }
        __syncthreads();
        mma_tile<8>(As, Bs, acc, ty, tx);
        __syncthreads();
    }

#pragma unroll
    for (int i = 0; i < 8; i++) {
        int m = m0 + ty * 8 + i;
#pragma unroll
        for (int j = 0; j < 8; j++) {
            int n = n0 + tx * 8 + j;
            out[(size_t)(b * N_ + m) * C_ + n] = acc[i][j] + projb[n];
        }
    }
}

// ---------------- launch -----------------------------------------------------
extern "C" void kernel_launch(void* const* d_in, const int* in_sizes, int n_in,
                              void* d_out, int out_size) {
    const float* x      = (const float*)d_in[0];
    const float* wq_w   = (const float*)d_in[1];
    const float* wq_b   = (const float*)d_in[2];
    const float* wkv_w  = (const float*)d_in[3];
    const float* wkv_b  = (const float*)d_in[4];
    const float* dwc_w  = (const float*)d_in[5];
    const float* dwc_b  = (const float*)d_in[6];
    const float* proj_w = (const float*)d_in[7];
    const float* proj_b = (const float*)d_in[8];
    float* out = (float*)d_out;

    k_init<<<324, 256>>>();
    k_gemm1<<<dim3(11, 512), 256>>>(x, wq_w, wq_b, wkv_w, wkv_b);
    k_qnorm<<<4096, 256>>>();
    k_knorm<<<256, 256>>>();
    k_scales<<<1, 288>>>();
    k_kvacc<<<dim3(8, 16), 576>>>();
    k_dwc<<<18432, 256>>>(dwc_w, dwc_b);
    k_projsum<<<324, 256>>>(proj_w);
    k_mker<<<dim3(9, 16, 16), 256>>>(proj_w);
    k_gemm2<<<dim3(9, 32, 16), 256>>>(proj_b, out);
}

// round 7
// speedup vs baseline: 3.4908x; 3.4804x over previous
#include <cuda_runtime.h>
#include <cuda_bf16.h>
#include <cstdint>
#include <math.h>

#define B_   16
#define N_   4096
#define C_   1152
#define H_   16
#define HD_  72
#define KV2  144
#define NCAT 1296          // C_ + KV2
#define MTOT (B_*N_)       // 65536
#define KA2  1224          // C_ + HD_  (gemm2 A width)

// ---------------- scratch (static device globals) --------------------------
__device__ float g_q[(size_t)MTOT * C_];          // 302 MB
__device__ float g_kvlin[(size_t)MTOT * KV2];     // 37.7 MB
__device__ float g_kv[B_ * HD_ * HD_];
__device__ float g_qsum[B_ * H_ * 2];
__device__ float g_ksum[B_ * 2];
__device__ float g_scaleq[B_ * H_];
__device__ float g_scalek[B_];

__device__ __nv_bfloat16 g_Xhi[(size_t)MTOT * C_];    // 151 MB
__device__ __nv_bfloat16 g_Xlo[(size_t)MTOT * C_];
__device__ __nv_bfloat16 g_B1hi[(size_t)NCAT * C_];   // Wcat^T [n][k]
__device__ __nv_bfloat16 g_B1lo[(size_t)NCAT * C_];
__device__ __nv_bfloat16 g_A2hi[(size_t)MTOT * KA2];  // [qf | vd]
__device__ __nv_bfloat16 g_A2lo[(size_t)MTOT * KA2];
__device__ __nv_bfloat16 g_B2hi[(size_t)B_ * C_ * KA2]; // [Mt | Pt] per b
__device__ __nv_bfloat16 g_B2lo[(size_t)B_ * C_ * KA2];

// ====================== PTX helpers =========================================
__device__ __forceinline__ uint32_t smem_u32(const void* p) {
    uint32_t a;
    asm("{ .reg .u64 t; cvta.to.shared.u64 t, %1; cvt.u32.u64 %0, t; }" : "=r"(a) : "l"(p));
    return a;
}
__device__ __forceinline__ void cp16(uint32_t dst, const void* src, int sz) {
    asm volatile("cp.async.cg.shared.global [%0], [%1], 16, %2;"
                 :: "r"(dst), "l"(src), "r"(sz) : "memory");
}
__device__ __forceinline__ void cp_commit() { asm volatile("cp.async.commit_group;" ::: "memory"); }
template <int NN> __device__ __forceinline__ void cp_wait() {
    asm volatile("cp.async.wait_group %0;" :: "n"(NN) : "memory");
}
__device__ __forceinline__ uint32_t swz(uint32_t off) { return off ^ ((off >> 3) & 0x70); }

__device__ __forceinline__ void ldsm4(uint32_t* r, uint32_t addr) {
    asm volatile("ldmatrix.sync.aligned.m8n8.x4.shared.b16 {%0,%1,%2,%3}, [%4];"
        : "=r"(r[0]), "=r"(r[1]), "=r"(r[2]), "=r"(r[3]) : "r"(addr));
}
__device__ __forceinline__ void mma16816(float* c, const uint32_t* a, const uint32_t* b) {
    asm volatile("mma.sync.aligned.m16n8k16.row.col.f32.bf16.bf16.f32 "
        "{%0,%1,%2,%3}, {%4,%5,%6,%7}, {%8,%9}, {%0,%1,%2,%3};"
        : "+f"(c[0]), "+f"(c[1]), "+f"(c[2]), "+f"(c[3])
        : "r"(a[0]), "r"(a[1]), "r"(a[2]), "r"(a[3]), "r"(b[0]), "r"(b[1]));
}

#define SMEM_BYTES (1024 + 3 * 32768)

// ====================== staged tile fill (cp.async, SW128) ==================
template <int KA, int NTOT>
__device__ __forceinline__ void fill_stage(
    uint32_t sb, int s, int kt,
    const __nv_bfloat16* __restrict__ Ahi, const __nv_bfloat16* __restrict__ Alo,
    int arow0,
    const __nv_bfloat16* __restrict__ Bhi, const __nv_bfloat16* __restrict__ Blo,
    size_t boff, int n0) {
    const int K3 = 3 * KA;
    uint32_t ab = sb + 1024u + (uint32_t)s * 32768u;
    uint32_t bb = ab + 16384u;
    int tid = threadIdx.x;
#pragma unroll
    for (int i = 0; i < 4; i++) {
        int q = tid + i * 256;
        int r = q >> 3, c16 = q & 7;
        int k3 = kt * 64 + c16 * 8;
        bool kin = k3 < K3;
        int pass = kin ? (k3 / KA) : 0;
        int kloc = kin ? (k3 - pass * KA) : 0;
        uint32_t sw = swz((uint32_t)(r * 128 + c16 * 16));
        const __nv_bfloat16* asrc =
            (pass == 1 ? Alo : Ahi) + (size_t)(arow0 + r) * KA + kloc;
        cp16(ab + sw, asrc, kin ? 16 : 0);
        int n = n0 + r;
        bool bin = kin && (n < NTOT);
        const __nv_bfloat16* bsrc =
            (pass == 2 ? Blo : Bhi) + boff + (size_t)(bin ? n : 0) * KA + kloc;
        cp16(bb + sw, bsrc, bin ? 16 : 0);
    }
}

// ====================== HMMA GEMM (mma.sync, 3x-bf16 split) =================
template <int KA, int KT, int NTOT, bool IS_G1>
__global__ __launch_bounds__(256) void k_hgemm(
    const __nv_bfloat16* __restrict__ Ahi, const __nv_bfloat16* __restrict__ Alo,
    const __nv_bfloat16* __restrict__ Bhi, const __nv_bfloat16* __restrict__ Blo,
    float* __restrict__ out0, float* __restrict__ out1,
    const float* __restrict__ bias0, const float* __restrict__ bias1) {
    extern __shared__ char smem[];
    uint32_t sb = smem_u32(smem);
    int tid = threadIdx.x;
    int lane = tid & 31, warp = tid >> 5;
    int wm = warp & 1, wn = warp >> 1;        // warp grid 2 x 4
    int mi = lane >> 3, r8 = lane & 7;

    int n0 = blockIdx.x * 128;
    int arow0 = IS_G1 ? (int)(blockIdx.y * 128)
                      : (int)(blockIdx.z * 4096 + blockIdx.y * 128);
    size_t boff = IS_G1 ? 0 : (size_t)blockIdx.z * NTOT * KA;

    // ldmatrix per-lane offsets
    int a_row = wm * 64 + (mi & 1) * 8 + r8;   // + mt*16
    int a_k8  = (mi >> 1) * 8;                 // + kk*16
    int b_row = wn * 32 + (mi >> 1) * 8 + r8;  // + bt*16
    int b_k8  = (mi & 1) * 8;

    float acc[16][4];
#pragma unroll
    for (int i = 0; i < 16; i++)
#pragma unroll
        for (int j = 0; j < 4; j++) acc[i][j] = 0.f;

    fill_stage<KA, NTOT>(sb, 0, 0, Ahi, Alo, arow0, Bhi, Blo, boff, n0); cp_commit();
    fill_stage<KA, NTOT>(sb, 1, 1, Ahi, Alo, arow0, Bhi, Blo, boff, n0); cp_commit();

    for (int kt = 0; kt < KT; kt++) {
        int buf = kt % 3;
        if (kt + 2 < KT) {
            fill_stage<KA, NTOT>(sb, (kt + 2) % 3, kt + 2, Ahi, Alo, arow0,
                                 Bhi, Blo, boff, n0);
            cp_commit();
            cp_wait<2>();
        } else if (kt + 1 < KT) {
            cp_wait<1>();
        } else {
            cp_wait<0>();
        }
        __syncthreads();

        uint32_t ab = sb + 1024u + (uint32_t)buf * 32768u;
        uint32_t bb = ab + 16384u;
#pragma unroll
        for (int kk = 0; kk < 4; kk++) {
            uint32_t afr[4][4], bfr[2][4];
#pragma unroll
            for (int mt = 0; mt < 4; mt++)
                ldsm4(afr[mt], ab + swz((uint32_t)((a_row + mt * 16) * 128
                                                   + (kk * 16 + a_k8) * 2)));
#pragma unroll
            for (int bt = 0; bt < 2; bt++)
                ldsm4(bfr[bt], bb + swz((uint32_t)((b_row + bt * 16) * 128
                                                   + (kk * 16 + b_k8) * 2)));
#pragma unroll
            for (int mt = 0; mt < 4; mt++)
#pragma unroll
                for (int nt = 0; nt < 4; nt++)
                    mma16816(acc[mt * 4 + nt], afr[mt], &bfr[nt >> 1][(nt & 1) * 2]);
        }
        __syncthreads();
    }

    // ---- epilogue: fragment -> global (float2 stores) ----
    int crow = lane >> 2, ccol = (lane & 3) * 2;
#pragma unroll
    for (int mt = 0; mt < 4; mt++) {
#pragma unroll
        for (int nt = 0; nt < 4; nt++) {
            int col = n0 + wn * 32 + nt * 8 + ccol;
            const float* cp = acc[mt * 4 + nt];
#pragma unroll
            for (int half = 0; half < 2; half++) {
                int row = arow0 + wm * 64 + mt * 16 + crow + half * 8;
                float v0 = cp[half * 2], v1 = cp[half * 2 + 1];
                if (IS_G1) {
                    if (col < C_) {
                        float2 o = make_float2(v0 + bias0[col], v1 + bias0[col + 1]);
                        *(float2*)&out0[(size_t)row * C_ + col] = o;
                    } else if (col < NCAT) {
                        int c2 = col - C_;
                        float2 o = make_float2(v0 + bias1[c2], v1 + bias1[c2 + 1]);
                        *(float2*)&out1[(size_t)row * KV2 + c2] = o;
                    }
                } else {
                    float2 o = make_float2(v0 + bias0[col], v1 + bias0[col + 1]);
                    *(float2*)&out0[(size_t)row * C_ + col] = o;
                }
            }
        }
    }
}

// ====================== split / precompute kernels ==========================
__device__ __forceinline__ void split_bf16(float v, __nv_bfloat16& hi, __nv_bfloat16& lo) {
    hi = __float2bfloat16(v);
    lo = __float2bfloat16(v - __bfloat162float(hi));
}

__global__ void k_xsplit(const float* __restrict__ x) {
    size_t i = (size_t)blockIdx.x * 256 + threadIdx.x;
    __nv_bfloat16 h, l;
    split_bf16(x[i], h, l);
    g_Xhi[i] = h; g_Xlo[i] = l;
}

__global__ void k_wsplit(const float* __restrict__ wq, const float* __restrict__ wkv) {
    int i = blockIdx.x * 256 + threadIdx.x;           // over NCAT*C_
    int n = i / C_, k = i - n * C_;
    float v = (n < C_) ? wq[(size_t)k * C_ + n] : wkv[(size_t)k * KV2 + (n - C_)];
    __nv_bfloat16 h, l;
    split_bf16(v, h, l);
    g_B1hi[i] = h; g_B1lo[i] = l;
}

// qf = scaleq * relu(q)^3 -> A2 cols [0, C_)
__global__ void k_qf() {
    size_t i = (size_t)blockIdx.x * 256 + threadIdx.x;   // over MTOT*C_
    size_t row = i / C_;
    int c = (int)(i - row * C_);
    float v = g_q[i];
    float s = g_scaleq[((int)(row >> 12)) * H_ + c / HD_];
    float r = fmaxf(v, 0.f);
    float q3 = s * r * r * r;
    __nv_bfloat16 h, l;
    split_bf16(q3, h, l);
    size_t o = row * KA2 + c;
    g_A2hi[o] = h; g_A2lo[o] = l;
}

// ---------------- init ------------------------------------------------------
__global__ void k_init() {
    int i = blockIdx.x * blockDim.x + threadIdx.x;
    if (i < B_ * HD_ * HD_) g_kv[i] = 0.f;
    if (i < B_ * H_ * 2)    g_qsum[i] = 0.f;
    if (i < B_ * 2)         g_ksum[i] = 0.f;
}

// ---------------- reductions -------------------------------------------------
__device__ __forceinline__ void block_reduce2(float& s2, float& s6) {
#pragma unroll
    for (int o = 16; o; o >>= 1) {
        s2 += __shfl_down_sync(0xffffffffu, s2, o);
        s6 += __shfl_down_sync(0xffffffffu, s6, o);
    }
    __shared__ float sh2[8], sh6[8];
    int w = threadIdx.x >> 5, l = threadIdx.x & 31;
    if (l == 0) { sh2[w] = s2; sh6[w] = s6; }
    __syncthreads();
    if (threadIdx.x == 0) {
        float a = 0.f, c = 0.f;
#pragma unroll
        for (int i = 0; i < 8; i++) { a += sh2[i]; c += sh6[i]; }
        s2 = a; s6 = c;
    }
}

__global__ void k_qnorm() {
    int bh = blockIdx.x >> 4;
    int split = blockIdx.x & 15;
    int b = bh >> 4, h = bh & 15;
    const float* base = g_q + (size_t)(b * N_ + split * 256) * C_ + h * HD_;
    float s2 = 0.f, s6 = 0.f;
    for (int e = threadIdx.x; e < 256 * HD_; e += 256) {
        int r = e / HD_, d = e % HD_;
        float v = base[(size_t)r * C_ + d];
        float rr = fmaxf(v, 0.f);
        float r2 = rr * rr;  s2 += r2;
        float r3 = r2 * rr;  s6 += r3 * r3;
    }
    block_reduce2(s2, s6);
    if (threadIdx.x == 0) {
        atomicAdd(&g_qsum[bh * 2], s2);
        atomicAdd(&g_qsum[bh * 2 + 1], s6);
    }
}

__global__ void k_knorm() {
    int b = blockIdx.x >> 4;
    int split = blockIdx.x & 15;
    const float* base = g_kvlin + (size_t)(b * N_ + split * 256) * KV2;
    float s2 = 0.f, s6 = 0.f;
    for (int e = threadIdx.x; e < 256 * HD_; e += 256) {
        int r = e / HD_, d = e % HD_;
        float v = base[(size_t)r * KV2 + d];
        float rr = fmaxf(v, 0.f);
        float r2 = rr * rr;  s2 += r2;
        float r3 = r2 * rr;  s6 += r3 * r3;
    }
    block_reduce2(s2, s6);
    if (threadIdx.x == 0) {
        atomicAdd(&g_ksum[b * 2], s2);
        atomicAdd(&g_ksum[b * 2 + 1], s6);
    }
}

__global__ void k_scales() {
    int i = threadIdx.x;
    if (i < B_ * H_) {
        float s2 = g_qsum[i * 2], s6 = g_qsum[i * 2 + 1];
        g_scaleq[i] = (s6 > 0.f) ? sqrtf(s2 / s6) : 0.f;
    } else if (i < B_ * H_ + B_) {
        int b = i - B_ * H_;
        float s2 = g_ksum[b * 2], s6 = g_ksum[b * 2 + 1];
        g_scalek[b] = (s6 > 0.f) ? sqrtf(s2 / s6) : 0.f;
    }
}

// ---------------- kv = k_f^T @ v ---------------------------------------------
__global__ __launch_bounds__(576) void k_kvacc() {
    __shared__ float ks[16][72], vs[16][72];
    int b = blockIdx.y;
    int n0 = blockIdx.x * 512;
    int tid = threadIdx.x;
    float acc[9] = {};
    int od[9], oe[9];
#pragma unroll
    for (int j = 0; j < 9; j++) { int o = tid + j * 576; od[j] = o / 72; oe[j] = o % 72; }

    for (int nt = 0; nt < 512; nt += 16) {
        __syncthreads();
        for (int e = tid; e < 16 * 72; e += 576) {
            int r = e / 72, d = e % 72;
            const float* p = g_kvlin + (size_t)(b * N_ + n0 + nt + r) * KV2;
            float kvv = p[d];
            float rr = fmaxf(kvv, 0.f);
            ks[r][d] = rr * rr * rr;
            vs[r][d] = p[72 + d];
        }
        __syncthreads();
#pragma unroll
        for (int r = 0; r < 16; r++)
#pragma unroll
            for (int j = 0; j < 9; j++) acc[j] += ks[r][od[j]] * vs[r][oe[j]];
    }
    float s = g_scalek[b];
#pragma unroll
    for (int j = 0; j < 9; j++)
        atomicAdd(&g_kv[b * 5184 + tid + j * 576], acc[j] * s);
}

// ---------------- depthwise conv -> A2 cols [C_, KA2) -------------------------
__global__ void k_dwc(const float* __restrict__ w, const float* __restrict__ bias) {
    int idx = blockIdx.x * blockDim.x + threadIdx.x;
    int d = idx % HD_;
    int t = idx / HD_;
    int n = t % N_;
    int b = t / N_;
    int y = n >> 6, xx = n & 63;
    float acc = bias[d];
#pragma unroll
    for (int ky = 0; ky < 3; ky++) {
        int yy = y + ky - 1;
        if ((unsigned)yy < 64u) {
#pragma unroll
            for (int kx = 0; kx < 3; kx++) {
                int xc = xx + kx - 1;
                if ((unsigned)xc < 64u)
                    acc += g_kvlin[(size_t)(b * N_ + yy * 64 + xc) * KV2 + 72 + d]
                         * w[d * 9 + ky * 3 + kx];
            }
        }
    }
    __nv_bfloat16 h, l;
    split_bf16(acc, h, l);
    size_t o = (size_t)(b * N_ + n) * KA2 + C_ + d;
    g_A2hi[o] = h; g_A2lo[o] = l;
}

// ---------------- proj_sum -> B2 rows [C_, KA2) for every batch ---------------
__global__ void k_projsum(const float* __restrict__ proj) {
    int idx = blockIdx.x * blockDim.x + threadIdx.x;   // 72*1152
    if (idx >= HD_ * C_) return;
    int c = idx / HD_, d = idx % HD_;
    float s = 0.f;
#pragma unroll
    for (int h = 0; h < H_; h++) s += proj[(size_t)(h * HD_ + d) * C_ + c];
    __nv_bfloat16 hh, ll;
    split_bf16(s, hh, ll);
#pragma unroll
    for (int b = 0; b < B_; b++) {
        size_t o = ((size_t)b * C_ + c) * KA2 + C_ + d;
        g_B2hi[o] = hh; g_B2lo[o] = ll;
    }
}

// ---------------- Mt[b][c][k=h*72+d] = sum_e kv[b][d][e] * proj[h*72+e][c] ----
__global__ __launch_bounds__(256) void k_mker(const float* __restrict__ proj) {
    __shared__ float kvs[72 * 72];
    int b = blockIdx.z, h = blockIdx.y, ct = blockIdx.x;
    int tid = threadIdx.x;
    for (int e = tid; e < 5184; e += 256) kvs[e] = g_kv[b * 5184 + e];
    __syncthreads();
    int c = ct * 128 + (tid & 127);
    int dbase = (tid >> 7) * 36;
    float acc[36] = {};
#pragma unroll 8
    for (int e2 = 0; e2 < 72; e2++) {
        float p = proj[(size_t)(h * HD_ + e2) * C_ + c];
#pragma unroll
        for (int dd = 0; dd < 36; dd++)
            acc[dd] += kvs[(dbase + dd) * 72 + e2] * p;
    }
    size_t base = ((size_t)b * C_ + c) * KA2 + h * HD_ + dbase;
#pragma unroll
    for (int dd = 0; dd < 36; dd++) {
        __nv_bfloat16 hh, ll;
        split_bf16(acc[dd], hh, ll);
        g_B2hi[base + dd] = hh; g_B2lo[base + dd] = ll;
    }
}

// ---------------- launch ------------------------------------------------------
extern "C" void kernel_launch(void* const* d_in, const int* in_sizes, int n_in,
                              void* d_out, int out_size) {
    const float* x      = (const float*)d_in[0];
    const float* wq_w   = (const float*)d_in[1];
    const float* wq_b   = (const float*)d_in[2];
    const float* wkv_w  = (const float*)d_in[3];
    const float* wkv_b  = (const float*)d_in[4];
    const float* dwc_w  = (const float*)d_in[5];
    const float* dwc_b  = (const float*)d_in[6];
    const float* proj_w = (const float*)d_in[7];
    const float* proj_b = (const float*)d_in[8];
    float* out = (float*)d_out;

    cudaFuncSetAttribute(k_hgemm<C_, 54, NCAT, true>,
                         cudaFuncAttributeMaxDynamicSharedMemorySize, SMEM_BYTES);
    cudaFuncSetAttribute(k_hgemm<KA2, 58, C_, false>,
                         cudaFuncAttributeMaxDynamicSharedMemorySize, SMEM_BYTES);

    __nv_bfloat16 *xhi, *xlo, *b1hi, *b1lo, *a2hi, *a2lo, *b2hi, *b2lo;
    float *gq, *gkvlin;
    cudaGetSymbolAddress((void**)&xhi,  g_Xhi);
    cudaGetSymbolAddress((void**)&xlo,  g_Xlo);
    cudaGetSymbolAddress((void**)&b1hi, g_B1hi);
    cudaGetSymbolAddress((void**)&b1lo, g_B1lo);
    cudaGetSymbolAddress((void**)&a2hi, g_A2hi);
    cudaGetSymbolAddress((void**)&a2lo, g_A2lo);
    cudaGetSymbolAddress((void**)&b2hi, g_B2hi);
    cudaGetSymbolAddress((void**)&b2lo, g_B2lo);
    cudaGetSymbolAddress((void**)&gq,     g_q);
    cudaGetSymbolAddress((void**)&gkvlin, g_kvlin);

    k_init<<<324, 256>>>();
    k_xsplit<<<(int)((MTOT * (size_t)C_) / 256), 256>>>(x);
    k_wsplit<<<(NCAT * C_) / 256, 256>>>(wq_w, wkv_w);

    // GEMM1: [x] @ [wq|wkv]  -> g_q, g_kvlin   (3x-bf16, K3=3456)
    k_hgemm<C_, 54, NCAT, true><<<dim3(11, 512), 256, SMEM_BYTES>>>(
        xhi, xlo, b1hi, b1lo, gq, gkvlin, wq_b, wkv_b);

    k_qnorm<<<4096, 256>>>();
    k_knorm<<<256, 256>>>();
    k_scales<<<1, 288>>>();
    k_kvacc<<<dim3(8, 16), 576>>>();
    k_dwc<<<18432, 256>>>(dwc_w, dwc_b);
    k_qf<<<(int)((MTOT * (size_t)C_) / 256), 256>>>();
    k_projsum<<<324, 256>>>(proj_w);
    k_mker<<<dim3(9, 16, 16), 256>>>(proj_w);

    // GEMM2: [qf|vd] @ [Mt|Pt]^T + proj_b -> out   (3x-bf16, K3=3672)
    k_hgemm<KA2, 58, C_, false><<<dim3(9, 32, 16), 256, SMEM_BYTES>>>(
        a2hi, a2lo, b2hi, b2lo, out, nullptr, proj_b, nullptr);
}